// round 7
// baseline (speedup 1.0000x reference)
#include <cuda_runtime.h>
#include <math.h>

#define N_NODES 50000
#define N_EDGES 1250000
#define D 64
#define L 3

#define CNT_PAD 53248  // 52 * 1024, >= N_NODES, multiple of 4

// Scratch (allocation-free).
__device__ float g_agg[N_NODES * D];
__device__ float g_h[N_NODES * D];
__device__ int   g_cnt[CNT_PAD];
__device__ int   g_off[N_NODES + 1];
__device__ int   g_cursor[N_NODES];
__device__ int2  g_csr[N_EDGES];     // .x = src node, .y = weight bits

// ---------------------------------------------------------------------------
// Copy input h into out[:, 0:64]; zero the (padded) CSR counters.
__global__ void copy_h_zero_cnt_kernel(const float* __restrict__ h,
                                       float* __restrict__ out) {
    int i = blockIdx.x * blockDim.x + threadIdx.x;
    if (i < CNT_PAD) g_cnt[i] = 0;
    if (i >= N_NODES * 16) return;
    int node = i >> 4;
    int c = i & 15;
    float4 v = ((const float4*)h)[i];
    ((float4*)(out + (size_t)node * 256))[c] = v;
}

// ---------------------------------------------------------------------------
// CSR build pass 1: count in-degree per dst node. 2 edges/thread for ILP.
__global__ void count_kernel(const int* __restrict__ dst) {
    int i = blockIdx.x * blockDim.x + threadIdx.x;
    if (i >= N_EDGES / 2) return;
    int2 d2 = ((const int2*)dst)[i];
    atomicAdd(&g_cnt[d2.x], 1);
    atomicAdd(&g_cnt[d2.y], 1);
}

// ---------------------------------------------------------------------------
// CSR build pass 2: exclusive prefix scan (single block, 1024 thr, int4 loads).
__global__ void scan_kernel() {
    __shared__ int partial[1024];
    const int CHUNK = 52;                 // multiple of 4; 52*1024 = CNT_PAD
    int t = threadIdx.x;
    int start = t * CHUNK;

    int sum = 0;
    #pragma unroll
    for (int i = 0; i < CHUNK / 4; i++) {
        int4 v = ((const int4*)g_cnt)[start / 4 + i];
        sum += v.x + v.y + v.z + v.w;     // padding is zero
    }
    partial[t] = sum;
    __syncthreads();

    for (int off = 1; off < 1024; off <<= 1) {
        int v = (t >= off) ? partial[t - off] : 0;
        __syncthreads();
        partial[t] += v;
        __syncthreads();
    }

    int run = (t == 0) ? 0 : partial[t - 1];
    #pragma unroll 4
    for (int i = 0; i < CHUNK; i++) {
        int idx = start + i;
        if (idx < N_NODES) {
            g_off[idx] = run;
            g_cursor[idx] = run;
            run += g_cnt[idx];
        }
    }
    if (t == 0) g_off[N_NODES] = partial[1023];
}

// ---------------------------------------------------------------------------
// CSR build pass 3: scatter edges into dst-sorted order. 2 edges/thread.
__global__ void fill_kernel(const int* __restrict__ src,
                            const int* __restrict__ dst,
                            const float* __restrict__ ew) {
    int i = blockIdx.x * blockDim.x + threadIdx.x;
    if (i >= N_EDGES / 2) return;
    int2   d2 = ((const int2*)dst)[i];
    int2   s2 = ((const int2*)src)[i];
    float2 w2 = ((const float2*)ew)[i];
    int p0 = atomicAdd(&g_cursor[d2.x], 1);
    int p1 = atomicAdd(&g_cursor[d2.y], 1);
    g_csr[p0] = make_int2(s2.x, __float_as_int(w2.x));
    g_csr[p1] = make_int2(s2.y, __float_as_int(w2.y));
}

// ---------------------------------------------------------------------------
// Pull aggregation: agg[n] = sum_{edges into n} h[src] * w. Atomic-free,
// no barrier, no smem. 4 threads per node, each owning 16 columns
// (4 float4 accumulators). Edge loop unrolled by 2 -> 8 independent
// LDG.128 row loads in flight per thread (high MLP).
__global__ void gather_kernel(const float* __restrict__ hext, int use_ext) {
    int idx = blockIdx.x * blockDim.x + threadIdx.x;
    int node = idx >> 2;
    if (node >= N_NODES) return;
    int q = idx & 3;    // owns columns q*16 .. q*16+15

    const float4* __restrict__ hq =
        (use_ext ? (const float4*)hext : (const float4*)g_h) + q * 4;

    int beg = g_off[node];
    int end = g_off[node + 1];

    float4 a0 = make_float4(0.f, 0.f, 0.f, 0.f);
    float4 a1 = a0, a2 = a0, a3 = a0;

    int j = beg;
    for (; j + 2 <= end; j += 2) {
        int2 e0 = g_csr[j];
        int2 e1 = g_csr[j + 1];
        float w0 = __int_as_float(e0.y);
        float w1 = __int_as_float(e1.y);
        const float4* r0 = hq + e0.x * 16;
        const float4* r1 = hq + e1.x * 16;
        float4 u0 = r0[0], u1 = r0[1], u2 = r0[2], u3 = r0[3];
        float4 v0 = r1[0], v1 = r1[1], v2 = r1[2], v3 = r1[3];
        a0.x += u0.x * w0; a0.y += u0.y * w0; a0.z += u0.z * w0; a0.w += u0.w * w0;
        a1.x += u1.x * w0; a1.y += u1.y * w0; a1.z += u1.z * w0; a1.w += u1.w * w0;
        a2.x += u2.x * w0; a2.y += u2.y * w0; a2.z += u2.z * w0; a2.w += u2.w * w0;
        a3.x += u3.x * w0; a3.y += u3.y * w0; a3.z += u3.z * w0; a3.w += u3.w * w0;
        a0.x += v0.x * w1; a0.y += v0.y * w1; a0.z += v0.z * w1; a0.w += v0.w * w1;
        a1.x += v1.x * w1; a1.y += v1.y * w1; a1.z += v1.z * w1; a1.w += v1.w * w1;
        a2.x += v2.x * w1; a2.y += v2.y * w1; a2.z += v2.z * w1; a2.w += v2.w * w1;
        a3.x += v3.x * w1; a3.y += v3.y * w1; a3.z += v3.z * w1; a3.w += v3.w * w1;
    }
    if (j < end) {
        int2 e0 = g_csr[j];
        float w0 = __int_as_float(e0.y);
        const float4* r0 = hq + e0.x * 16;
        float4 u0 = r0[0], u1 = r0[1], u2 = r0[2], u3 = r0[3];
        a0.x += u0.x * w0; a0.y += u0.y * w0; a0.z += u0.z * w0; a0.w += u0.w * w0;
        a1.x += u1.x * w0; a1.y += u1.y * w0; a1.z += u1.z * w0; a1.w += u1.w * w0;
        a2.x += u2.x * w0; a2.y += u2.y * w0; a2.z += u2.z * w0; a2.w += u2.w * w0;
        a3.x += u3.x * w0; a3.y += u3.y * w0; a3.z += u3.z * w0; a3.w += u3.w * w0;
    }

    float4* dst4 = (float4*)g_agg + node * 16 + q * 4;
    dst4[0] = a0; dst4[1] = a1; dst4[2] = a2; dst4[3] = a3;
}

// ---------------------------------------------------------------------------
// Dense transform: h_next = agg @ W + b, optional tanh. (R3-proven: 20.6us)
__global__ void gemm_bias_act_kernel(const float* __restrict__ W,
                                     const float* __restrict__ b,
                                     float* __restrict__ out,
                                     int out_col_off,
                                     int do_tanh) {
    __shared__ __align__(16) float AsT[64][68];
    __shared__ __align__(16) float Wsm[64 * 64];
    __shared__ float bsh[64];

    int t = threadIdx.x;  // 256 threads
    int rowBase = blockIdx.x * 64;

    #pragma unroll
    for (int i = t; i < 64 * 64; i += 256) Wsm[i] = W[i];
    if (t < 64) bsh[t] = b[t];

    #pragma unroll
    for (int i = 0; i < 4; i++) {
        int idx = t + i * 256;
        int row = idx >> 4;
        int c4  = idx & 15;
        int grow = rowBase + row;
        float4 v = (grow < N_NODES) ? ((const float4*)g_agg)[grow * 16 + c4]
                                    : make_float4(0.f, 0.f, 0.f, 0.f);
        AsT[c4 * 4 + 0][row] = v.x;
        AsT[c4 * 4 + 1][row] = v.y;
        AsT[c4 * 4 + 2][row] = v.z;
        AsT[c4 * 4 + 3][row] = v.w;
    }
    __syncthreads();

    int tx = t & 15;
    int ty = t >> 4;

    float acc[4][4];
    #pragma unroll
    for (int i = 0; i < 4; i++)
        #pragma unroll
        for (int j = 0; j < 4; j++)
            acc[i][j] = bsh[tx * 4 + j];

    #pragma unroll 16
    for (int k = 0; k < 64; k++) {
        float4 a = *(const float4*)&AsT[k][ty * 4];
        float4 w = *(const float4*)&Wsm[k * 64 + tx * 4];
        acc[0][0] += a.x * w.x; acc[0][1] += a.x * w.y; acc[0][2] += a.x * w.z; acc[0][3] += a.x * w.w;
        acc[1][0] += a.y * w.x; acc[1][1] += a.y * w.y; acc[1][2] += a.y * w.z; acc[1][3] += a.y * w.w;
        acc[2][0] += a.z * w.x; acc[2][1] += a.z * w.y; acc[2][2] += a.z * w.z; acc[2][3] += a.z * w.w;
        acc[3][0] += a.w * w.x; acc[3][1] += a.w * w.y; acc[3][2] += a.w * w.z; acc[3][3] += a.w * w.w;
    }

    #pragma unroll
    for (int i = 0; i < 4; i++) {
        int grow = rowBase + ty * 4 + i;
        if (grow >= N_NODES) continue;
        float4 r = make_float4(acc[i][0], acc[i][1], acc[i][2], acc[i][3]);
        if (do_tanh) {
            r.x = tanhf(r.x); r.y = tanhf(r.y); r.z = tanhf(r.z); r.w = tanhf(r.w);
        }
        *(float4*)(g_h + (size_t)grow * 64 + tx * 4) = r;
        *(float4*)(out + (size_t)grow * 256 + out_col_off + tx * 4) = r;
    }
}

// ---------------------------------------------------------------------------
extern "C" void kernel_launch(void* const* d_in, const int* in_sizes, int n_in,
                              void* d_out, int out_size) {
    const float* h   = (const float*)d_in[0];  // [N, 64]
    const float* ew  = (const float*)d_in[1];  // [E]
    const float* Ws  = (const float*)d_in[2];  // [3, 64, 64]
    const float* bs  = (const float*)d_in[3];  // [3, 64]
    const int*   src = (const int*)d_in[4];    // [E]
    const int*   dst = (const int*)d_in[5];    // [E]
    float*       out = (float*)d_out;          // [N, 256]

    // out[:, 0:64] = h; zero degree counters.
    copy_h_zero_cnt_kernel<<<(N_NODES * 16 + 255) / 256, 256>>>(h, out);

    // Build CSR (by dst) once — graph is constant across layers.
    count_kernel<<<(N_EDGES / 2 + 255) / 256, 256>>>(dst);
    scan_kernel<<<1, 1024>>>();
    fill_kernel<<<(N_EDGES / 2 + 255) / 256, 256>>>(src, dst, ew);

    for (int l = 0; l < L; l++) {
        gather_kernel<<<(N_NODES * 4 + 255) / 256, 256>>>(h, (l == 0) ? 1 : 0);
        gemm_bias_act_kernel<<<(N_NODES + 63) / 64, 256>>>(
            Ws + l * 64 * 64, bs + l * 64, out, (l + 1) * 64, (l < L - 1) ? 1 : 0);
    }
}

// round 9
// speedup vs baseline: 1.3882x; 1.3882x over previous
#include <cuda_runtime.h>
#include <math.h>

#define N_NODES 50000
#define N_EDGES 1250000
#define D 64
#define L 3

#define CNT_PAD 53248  // 52 * 1024, >= N_NODES, multiple of 4

// Scratch (allocation-free).
__device__ float g_agg[N_NODES * D];
__device__ float g_h[N_NODES * D];
__device__ int   g_cnt[CNT_PAD];
__device__ int   g_off[N_NODES + 1];
__device__ int   g_cursor[N_NODES];
__device__ int2  g_csr[N_EDGES];     // .x = src node, .y = weight bits

// ---------------------------------------------------------------------------
// Copy input h into out[:, 0:64]; zero the (padded) CSR counters.
__global__ void copy_h_zero_cnt_kernel(const float* __restrict__ h,
                                       float* __restrict__ out) {
    int i = blockIdx.x * blockDim.x + threadIdx.x;
    if (i < CNT_PAD) g_cnt[i] = 0;
    if (i >= N_NODES * 16) return;
    int node = i >> 4;
    int c = i & 15;
    float4 v = ((const float4*)h)[i];
    ((float4*)(out + (size_t)node * 256))[c] = v;
}

// ---------------------------------------------------------------------------
// CSR build pass 1: count in-degree per dst node. 4 edges/thread for ILP
// (4 independent atomic chains in flight).
__global__ void count_kernel(const int* __restrict__ dst) {
    int i = blockIdx.x * blockDim.x + threadIdx.x;
    if (i >= N_EDGES / 4) return;
    int4 d4 = ((const int4*)dst)[i];
    atomicAdd(&g_cnt[d4.x], 1);
    atomicAdd(&g_cnt[d4.y], 1);
    atomicAdd(&g_cnt[d4.z], 1);
    atomicAdd(&g_cnt[d4.w], 1);
}

// ---------------------------------------------------------------------------
// CSR build pass 2: exclusive prefix scan (single block, 1024 thr, int4 loads).
__global__ void scan_kernel() {
    __shared__ int partial[1024];
    const int CHUNK = 52;                 // multiple of 4; 52*1024 = CNT_PAD
    int t = threadIdx.x;
    int start = t * CHUNK;

    int sum = 0;
    #pragma unroll
    for (int i = 0; i < CHUNK / 4; i++) {
        int4 v = ((const int4*)g_cnt)[start / 4 + i];
        sum += v.x + v.y + v.z + v.w;     // padding is zero
    }
    partial[t] = sum;
    __syncthreads();

    for (int off = 1; off < 1024; off <<= 1) {
        int v = (t >= off) ? partial[t - off] : 0;
        __syncthreads();
        partial[t] += v;
        __syncthreads();
    }

    int run = (t == 0) ? 0 : partial[t - 1];
    #pragma unroll 4
    for (int i = 0; i < CHUNK; i++) {
        int idx = start + i;
        if (idx < N_NODES) {
            g_off[idx] = run;
            g_cursor[idx] = run;
            run += g_cnt[idx];
        }
    }
    if (t == 0) g_off[N_NODES] = partial[1023];
}

// ---------------------------------------------------------------------------
// CSR build pass 3: scatter edges into dst-sorted order. 4 edges/thread.
__global__ void fill_kernel(const int* __restrict__ src,
                            const int* __restrict__ dst,
                            const float* __restrict__ ew) {
    int i = blockIdx.x * blockDim.x + threadIdx.x;
    if (i >= N_EDGES / 4) return;
    int4   d4 = ((const int4*)dst)[i];
    int4   s4 = ((const int4*)src)[i];
    float4 w4 = ((const float4*)ew)[i];
    int p0 = atomicAdd(&g_cursor[d4.x], 1);
    int p1 = atomicAdd(&g_cursor[d4.y], 1);
    int p2 = atomicAdd(&g_cursor[d4.z], 1);
    int p3 = atomicAdd(&g_cursor[d4.w], 1);
    g_csr[p0] = make_int2(s4.x, __float_as_int(w4.x));
    g_csr[p1] = make_int2(s4.y, __float_as_int(w4.y));
    g_csr[p2] = make_int2(s4.z, __float_as_int(w4.z));
    g_csr[p3] = make_int2(s4.w, __float_as_int(w4.w));
}

// ---------------------------------------------------------------------------
// Pull aggregation: agg[n] = sum_{edges into n} h[src] * w. Atomic-free.
// ONE WARP PER NODE: each lane owns 2 columns (float2). Per edge the warp
// issues one fully-coalesced 256B read; CSR entries are warp-broadcast.
// Zero intra-warp divergence; edge loop unrolled x4 for MLP.
__global__ void gather_kernel(const float* __restrict__ hext, int use_ext) {
    int gtid = blockIdx.x * blockDim.x + threadIdx.x;
    int node = gtid >> 5;
    if (node >= N_NODES) return;
    int lane = gtid & 31;

    const float2* __restrict__ h2 =
        use_ext ? (const float2*)hext : (const float2*)g_h;

    int beg = g_off[node];
    int end = g_off[node + 1];

    float2 acc = make_float2(0.f, 0.f);

    int j = beg;
    for (; j + 4 <= end; j += 4) {
        int2 e0 = g_csr[j];
        int2 e1 = g_csr[j + 1];
        int2 e2 = g_csr[j + 2];
        int2 e3 = g_csr[j + 3];
        float2 v0 = h2[e0.x * 32 + lane];
        float2 v1 = h2[e1.x * 32 + lane];
        float2 v2 = h2[e2.x * 32 + lane];
        float2 v3 = h2[e3.x * 32 + lane];
        float w0 = __int_as_float(e0.y);
        float w1 = __int_as_float(e1.y);
        float w2 = __int_as_float(e2.y);
        float w3 = __int_as_float(e3.y);
        acc.x += v0.x * w0; acc.y += v0.y * w0;
        acc.x += v1.x * w1; acc.y += v1.y * w1;
        acc.x += v2.x * w2; acc.y += v2.y * w2;
        acc.x += v3.x * w3; acc.y += v3.y * w3;
    }
    for (; j < end; j++) {
        int2 e = g_csr[j];
        float w = __int_as_float(e.y);
        float2 v = h2[e.x * 32 + lane];
        acc.x += v.x * w; acc.y += v.y * w;
    }

    ((float2*)g_agg)[node * 32 + lane] = acc;
}

// ---------------------------------------------------------------------------
// Dense transform: h_next = agg @ W + b, optional tanh. (R3-proven: 20.6us)
__global__ void gemm_bias_act_kernel(const float* __restrict__ W,
                                     const float* __restrict__ b,
                                     float* __restrict__ out,
                                     int out_col_off,
                                     int do_tanh) {
    __shared__ __align__(16) float AsT[64][68];
    __shared__ __align__(16) float Wsm[64 * 64];
    __shared__ float bsh[64];

    int t = threadIdx.x;  // 256 threads
    int rowBase = blockIdx.x * 64;

    #pragma unroll
    for (int i = t; i < 64 * 64; i += 256) Wsm[i] = W[i];
    if (t < 64) bsh[t] = b[t];

    #pragma unroll
    for (int i = 0; i < 4; i++) {
        int idx = t + i * 256;
        int row = idx >> 4;
        int c4  = idx & 15;
        int grow = rowBase + row;
        float4 v = (grow < N_NODES) ? ((const float4*)g_agg)[grow * 16 + c4]
                                    : make_float4(0.f, 0.f, 0.f, 0.f);
        AsT[c4 * 4 + 0][row] = v.x;
        AsT[c4 * 4 + 1][row] = v.y;
        AsT[c4 * 4 + 2][row] = v.z;
        AsT[c4 * 4 + 3][row] = v.w;
    }
    __syncthreads();

    int tx = t & 15;
    int ty = t >> 4;

    float acc[4][4];
    #pragma unroll
    for (int i = 0; i < 4; i++)
        #pragma unroll
        for (int j = 0; j < 4; j++)
            acc[i][j] = bsh[tx * 4 + j];

    #pragma unroll 16
    for (int k = 0; k < 64; k++) {
        float4 a = *(const float4*)&AsT[k][ty * 4];
        float4 w = *(const float4*)&Wsm[k * 64 + tx * 4];
        acc[0][0] += a.x * w.x; acc[0][1] += a.x * w.y; acc[0][2] += a.x * w.z; acc[0][3] += a.x * w.w;
        acc[1][0] += a.y * w.x; acc[1][1] += a.y * w.y; acc[1][2] += a.y * w.z; acc[1][3] += a.y * w.w;
        acc[2][0] += a.z * w.x; acc[2][1] += a.z * w.y; acc[2][2] += a.z * w.z; acc[2][3] += a.z * w.w;
        acc[3][0] += a.w * w.x; acc[3][1] += a.w * w.y; acc[3][2] += a.w * w.z; acc[3][3] += a.w * w.w;
    }

    #pragma unroll
    for (int i = 0; i < 4; i++) {
        int grow = rowBase + ty * 4 + i;
        if (grow >= N_NODES) continue;
        float4 r = make_float4(acc[i][0], acc[i][1], acc[i][2], acc[i][3]);
        if (do_tanh) {
            r.x = tanhf(r.x); r.y = tanhf(r.y); r.z = tanhf(r.z); r.w = tanhf(r.w);
        }
        *(float4*)(g_h + (size_t)grow * 64 + tx * 4) = r;
        *(float4*)(out + (size_t)grow * 256 + out_col_off + tx * 4) = r;
    }
}

// ---------------------------------------------------------------------------
extern "C" void kernel_launch(void* const* d_in, const int* in_sizes, int n_in,
                              void* d_out, int out_size) {
    const float* h   = (const float*)d_in[0];  // [N, 64]
    const float* ew  = (const float*)d_in[1];  // [E]
    const float* Ws  = (const float*)d_in[2];  // [3, 64, 64]
    const float* bs  = (const float*)d_in[3];  // [3, 64]
    const int*   src = (const int*)d_in[4];    // [E]
    const int*   dst = (const int*)d_in[5];    // [E]
    float*       out = (float*)d_out;          // [N, 256]

    // out[:, 0:64] = h; zero degree counters.
    copy_h_zero_cnt_kernel<<<(N_NODES * 16 + 255) / 256, 256>>>(h, out);

    // Build CSR (by dst) once — graph is constant across layers.
    count_kernel<<<(N_EDGES / 4 + 255) / 256, 256>>>(dst);
    scan_kernel<<<1, 1024>>>();
    fill_kernel<<<(N_EDGES / 4 + 255) / 256, 256>>>(src, dst, ew);

    for (int l = 0; l < L; l++) {
        gather_kernel<<<(N_NODES * 32 + 255) / 256, 256>>>(h, (l == 0) ? 1 : 0);
        gemm_bias_act_kernel<<<(N_NODES + 63) / 64, 256>>>(
            Ws + l * 64 * 64, bs + l * 64, out, (l + 1) * 64, (l < L - 1) ? 1 : 0);
    }
}

// round 10
// speedup vs baseline: 1.4085x; 1.0146x over previous
#include <cuda_runtime.h>
#include <math.h>

#define N_NODES 50000
#define N_EDGES 1250000
#define D 64
#define L 3

#define CNT_PAD 53248  // 52 * 1024, >= N_NODES, multiple of 4

// Scratch (allocation-free).
__device__ float g_agg[N_NODES * D];
__device__ float g_h[N_NODES * D];
__device__ int   g_cnt[CNT_PAD];
__device__ int   g_off[N_NODES + 1];
__device__ int   g_cursor[N_NODES];
__device__ int2  g_csr[N_EDGES];     // .x = src node, .y = weight bits

// ---------------------------------------------------------------------------
// Copy input h into out[:, 0:64]; zero the (padded) CSR counters.
__global__ void copy_h_zero_cnt_kernel(const float* __restrict__ h,
                                       float* __restrict__ out) {
    int i = blockIdx.x * blockDim.x + threadIdx.x;
    if (i < CNT_PAD) g_cnt[i] = 0;
    if (i >= N_NODES * 16) return;
    int node = i >> 4;
    int c = i & 15;
    float4 v = ((const float4*)h)[i];
    ((float4*)(out + (size_t)node * 256))[c] = v;
}

// ---------------------------------------------------------------------------
// CSR build pass 1: count in-degree per dst node. 4 edges/thread for ILP.
__global__ void count_kernel(const int* __restrict__ dst) {
    int i = blockIdx.x * blockDim.x + threadIdx.x;
    if (i >= N_EDGES / 4) return;
    int4 d4 = ((const int4*)dst)[i];
    atomicAdd(&g_cnt[d4.x], 1);
    atomicAdd(&g_cnt[d4.y], 1);
    atomicAdd(&g_cnt[d4.z], 1);
    atomicAdd(&g_cnt[d4.w], 1);
}

// ---------------------------------------------------------------------------
// CSR build pass 2: exclusive prefix scan (single block, 1024 thr, int4 loads).
__global__ void scan_kernel() {
    __shared__ int partial[1024];
    const int CHUNK = 52;                 // multiple of 4; 52*1024 = CNT_PAD
    int t = threadIdx.x;
    int start = t * CHUNK;

    int sum = 0;
    #pragma unroll
    for (int i = 0; i < CHUNK / 4; i++) {
        int4 v = ((const int4*)g_cnt)[start / 4 + i];
        sum += v.x + v.y + v.z + v.w;     // padding is zero
    }
    partial[t] = sum;
    __syncthreads();

    for (int off = 1; off < 1024; off <<= 1) {
        int v = (t >= off) ? partial[t - off] : 0;
        __syncthreads();
        partial[t] += v;
        __syncthreads();
    }

    int run = (t == 0) ? 0 : partial[t - 1];
    #pragma unroll 4
    for (int i = 0; i < CHUNK; i++) {
        int idx = start + i;
        if (idx < N_NODES) {
            g_off[idx] = run;
            g_cursor[idx] = run;
            run += g_cnt[idx];
        }
    }
    if (t == 0) g_off[N_NODES] = partial[1023];
}

// ---------------------------------------------------------------------------
// CSR build pass 3: scatter edges into dst-sorted order. 8 edges/thread
// (8 independent atomic chains in flight -> hides ATOMG latency).
__global__ void fill_kernel(const int* __restrict__ src,
                            const int* __restrict__ dst,
                            const float* __restrict__ ew) {
    int i = blockIdx.x * blockDim.x + threadIdx.x;
    if (i >= N_EDGES / 8) return;
    int4   dA = ((const int4*)dst)[i * 2];
    int4   dB = ((const int4*)dst)[i * 2 + 1];
    int4   sA = ((const int4*)src)[i * 2];
    int4   sB = ((const int4*)src)[i * 2 + 1];
    float4 wA = ((const float4*)ew)[i * 2];
    float4 wB = ((const float4*)ew)[i * 2 + 1];
    int p0 = atomicAdd(&g_cursor[dA.x], 1);
    int p1 = atomicAdd(&g_cursor[dA.y], 1);
    int p2 = atomicAdd(&g_cursor[dA.z], 1);
    int p3 = atomicAdd(&g_cursor[dA.w], 1);
    int p4 = atomicAdd(&g_cursor[dB.x], 1);
    int p5 = atomicAdd(&g_cursor[dB.y], 1);
    int p6 = atomicAdd(&g_cursor[dB.z], 1);
    int p7 = atomicAdd(&g_cursor[dB.w], 1);
    g_csr[p0] = make_int2(sA.x, __float_as_int(wA.x));
    g_csr[p1] = make_int2(sA.y, __float_as_int(wA.y));
    g_csr[p2] = make_int2(sA.z, __float_as_int(wA.z));
    g_csr[p3] = make_int2(sA.w, __float_as_int(wA.w));
    g_csr[p4] = make_int2(sB.x, __float_as_int(wB.x));
    g_csr[p5] = make_int2(sB.y, __float_as_int(wB.y));
    g_csr[p6] = make_int2(sB.z, __float_as_int(wB.z));
    g_csr[p7] = make_int2(sB.w, __float_as_int(wB.w));
}

// ---------------------------------------------------------------------------
// Pull aggregation: one warp per node, each lane owns 2 columns (float2).
// Fully coalesced 256B read per edge; CSR entries warp-broadcast.
// Edge loop unrolled x8 -> 8 independent row loads in flight.
__global__ void gather_kernel(const float* __restrict__ hext, int use_ext) {
    int gtid = blockIdx.x * blockDim.x + threadIdx.x;
    int node = gtid >> 5;
    if (node >= N_NODES) return;
    int lane = gtid & 31;

    const float2* __restrict__ h2 =
        use_ext ? (const float2*)hext : (const float2*)g_h;

    int beg = g_off[node];
    int end = g_off[node + 1];

    float2 acc = make_float2(0.f, 0.f);

    int j = beg;
    for (; j + 8 <= end; j += 8) {
        int2 e0 = g_csr[j];
        int2 e1 = g_csr[j + 1];
        int2 e2 = g_csr[j + 2];
        int2 e3 = g_csr[j + 3];
        int2 e4 = g_csr[j + 4];
        int2 e5 = g_csr[j + 5];
        int2 e6 = g_csr[j + 6];
        int2 e7 = g_csr[j + 7];
        float2 v0 = h2[e0.x * 32 + lane];
        float2 v1 = h2[e1.x * 32 + lane];
        float2 v2 = h2[e2.x * 32 + lane];
        float2 v3 = h2[e3.x * 32 + lane];
        float2 v4 = h2[e4.x * 32 + lane];
        float2 v5 = h2[e5.x * 32 + lane];
        float2 v6 = h2[e6.x * 32 + lane];
        float2 v7 = h2[e7.x * 32 + lane];
        acc.x += v0.x * __int_as_float(e0.y); acc.y += v0.y * __int_as_float(e0.y);
        acc.x += v1.x * __int_as_float(e1.y); acc.y += v1.y * __int_as_float(e1.y);
        acc.x += v2.x * __int_as_float(e2.y); acc.y += v2.y * __int_as_float(e2.y);
        acc.x += v3.x * __int_as_float(e3.y); acc.y += v3.y * __int_as_float(e3.y);
        acc.x += v4.x * __int_as_float(e4.y); acc.y += v4.y * __int_as_float(e4.y);
        acc.x += v5.x * __int_as_float(e5.y); acc.y += v5.y * __int_as_float(e5.y);
        acc.x += v6.x * __int_as_float(e6.y); acc.y += v6.y * __int_as_float(e6.y);
        acc.x += v7.x * __int_as_float(e7.y); acc.y += v7.y * __int_as_float(e7.y);
    }
    for (; j < end; j++) {
        int2 e = g_csr[j];
        float w = __int_as_float(e.y);
        float2 v = h2[e.x * 32 + lane];
        acc.x += v.x * w; acc.y += v.y * w;
    }

    ((float2*)g_agg)[node * 32 + lane] = acc;
}

// ---------------------------------------------------------------------------
// Dense transform: h_next = agg @ W + b, optional tanh.
// 64-row block, 128 threads, 8x4 register tile per thread:
//   per k-step: 3 LDS.128 + 32 FFMA (vs 2 LDS.128 + 16 FFMA before).
__global__ void gemm_bias_act_kernel(const float* __restrict__ W,
                                     const float* __restrict__ b,
                                     float* __restrict__ out,
                                     int out_col_off,
                                     int do_tanh) {
    __shared__ __align__(16) float AsT[64][68];
    __shared__ __align__(16) float Wsm[64 * 64];
    __shared__ float bsh[64];

    int t = threadIdx.x;  // 128 threads
    int rowBase = blockIdx.x * 64;

    #pragma unroll
    for (int i = 0; i < 8; i++)
        ((float4*)Wsm)[t + i * 128] = ((const float4*)W)[t + i * 128];
    if (t < 64) bsh[t] = b[t];

    #pragma unroll
    for (int i = 0; i < 8; i++) {
        int idx = t + i * 128;          // 0..1023
        int row = idx >> 4;             // 0..63
        int c4  = idx & 15;
        int grow = rowBase + row;
        float4 v = (grow < N_NODES) ? ((const float4*)g_agg)[grow * 16 + c4]
                                    : make_float4(0.f, 0.f, 0.f, 0.f);
        AsT[c4 * 4 + 0][row] = v.x;
        AsT[c4 * 4 + 1][row] = v.y;
        AsT[c4 * 4 + 2][row] = v.z;
        AsT[c4 * 4 + 3][row] = v.w;
    }
    __syncthreads();

    int tx = t & 15;   // cols tx*4 .. tx*4+3
    int ty = t >> 4;   // rows ty*8 .. ty*8+7

    float acc[8][4];
    #pragma unroll
    for (int i = 0; i < 8; i++)
        #pragma unroll
        for (int j = 0; j < 4; j++)
            acc[i][j] = bsh[tx * 4 + j];

    #pragma unroll 8
    for (int k = 0; k < 64; k++) {
        float4 alo = *(const float4*)&AsT[k][ty * 8];
        float4 ahi = *(const float4*)&AsT[k][ty * 8 + 4];
        float4 w   = *(const float4*)&Wsm[k * 64 + tx * 4];
        acc[0][0] += alo.x * w.x; acc[0][1] += alo.x * w.y; acc[0][2] += alo.x * w.z; acc[0][3] += alo.x * w.w;
        acc[1][0] += alo.y * w.x; acc[1][1] += alo.y * w.y; acc[1][2] += alo.y * w.z; acc[1][3] += alo.y * w.w;
        acc[2][0] += alo.z * w.x; acc[2][1] += alo.z * w.y; acc[2][2] += alo.z * w.z; acc[2][3] += alo.z * w.w;
        acc[3][0] += alo.w * w.x; acc[3][1] += alo.w * w.y; acc[3][2] += alo.w * w.z; acc[3][3] += alo.w * w.w;
        acc[4][0] += ahi.x * w.x; acc[4][1] += ahi.x * w.y; acc[4][2] += ahi.x * w.z; acc[4][3] += ahi.x * w.w;
        acc[5][0] += ahi.y * w.x; acc[5][1] += ahi.y * w.y; acc[5][2] += ahi.y * w.z; acc[5][3] += ahi.y * w.w;
        acc[6][0] += ahi.z * w.x; acc[6][1] += ahi.z * w.y; acc[6][2] += ahi.z * w.z; acc[6][3] += ahi.z * w.w;
        acc[7][0] += ahi.w * w.x; acc[7][1] += ahi.w * w.y; acc[7][2] += ahi.w * w.z; acc[7][3] += ahi.w * w.w;
    }

    #pragma unroll
    for (int i = 0; i < 8; i++) {
        int grow = rowBase + ty * 8 + i;
        if (grow >= N_NODES) continue;
        float4 r = make_float4(acc[i][0], acc[i][1], acc[i][2], acc[i][3]);
        if (do_tanh) {
            r.x = tanhf(r.x); r.y = tanhf(r.y); r.z = tanhf(r.z); r.w = tanhf(r.w);
        }
        *(float4*)(g_h + (size_t)grow * 64 + tx * 4) = r;
        *(float4*)(out + (size_t)grow * 256 + out_col_off + tx * 4) = r;
    }
}

// ---------------------------------------------------------------------------
extern "C" void kernel_launch(void* const* d_in, const int* in_sizes, int n_in,
                              void* d_out, int out_size) {
    const float* h   = (const float*)d_in[0];  // [N, 64]
    const float* ew  = (const float*)d_in[1];  // [E]
    const float* Ws  = (const float*)d_in[2];  // [3, 64, 64]
    const float* bs  = (const float*)d_in[3];  // [3, 64]
    const int*   src = (const int*)d_in[4];    // [E]
    const int*   dst = (const int*)d_in[5];    // [E]
    float*       out = (float*)d_out;          // [N, 256]

    // out[:, 0:64] = h; zero degree counters.
    copy_h_zero_cnt_kernel<<<(N_NODES * 16 + 255) / 256, 256>>>(h, out);

    // Build CSR (by dst) once — graph is constant across layers.
    count_kernel<<<(N_EDGES / 4 + 255) / 256, 256>>>(dst);
    scan_kernel<<<1, 1024>>>();
    fill_kernel<<<(N_EDGES / 8 + 255) / 256, 256>>>(src, dst, ew);

    for (int l = 0; l < L; l++) {
        gather_kernel<<<(N_NODES * 32 + 255) / 256, 256>>>(h, (l == 0) ? 1 : 0);
        gemm_bias_act_kernel<<<(N_NODES + 63) / 64, 128>>>(
            Ws + l * 64 * 64, bs + l * 64, out, (l + 1) * 64, (l < L - 1) ? 1 : 0);
    }
}

// round 11
// speedup vs baseline: 1.4868x; 1.0556x over previous
#include <cuda_runtime.h>
#include <cuda_fp16.h>
#include <math.h>

#define N_NODES 50000
#define N_EDGES 1250000
#define D 64
#define L 3

#define CNT_PAD 53248  // 52 * 1024, >= N_NODES, multiple of 4

// Scratch (allocation-free).
__device__ float   g_agg[N_NODES * D];
__device__ __half2 g_h16[N_NODES * (D / 2)];   // fp16 hidden state (gather input)
__device__ int     g_cnt[CNT_PAD];
__device__ int     g_off[N_NODES + 1];
__device__ int     g_cursor[N_NODES];
__device__ int2    g_csr[N_EDGES];   // .x = src node, .y = weight bits

// ---------------------------------------------------------------------------
// Copy input h into out[:, 0:64]; seed g_h16 = (half)h; zero CSR counters.
__global__ void copy_h_zero_cnt_kernel(const float* __restrict__ h,
                                       float* __restrict__ out) {
    int i = blockIdx.x * blockDim.x + threadIdx.x;
    if (i < CNT_PAD) g_cnt[i] = 0;
    if (i >= N_NODES * 16) return;
    int node = i >> 4;
    int c = i & 15;
    float4 v = ((const float4*)h)[i];
    ((float4*)(out + (size_t)node * 256))[c] = v;
    // two half2 per float4
    g_h16[node * 32 + c * 2 + 0] = __float22half2_rn(make_float2(v.x, v.y));
    g_h16[node * 32 + c * 2 + 1] = __float22half2_rn(make_float2(v.z, v.w));
}

// ---------------------------------------------------------------------------
// CSR build pass 1: count in-degree per dst node. 4 edges/thread for ILP.
__global__ void count_kernel(const int* __restrict__ dst) {
    int i = blockIdx.x * blockDim.x + threadIdx.x;
    if (i >= N_EDGES / 4) return;
    int4 d4 = ((const int4*)dst)[i];
    atomicAdd(&g_cnt[d4.x], 1);
    atomicAdd(&g_cnt[d4.y], 1);
    atomicAdd(&g_cnt[d4.z], 1);
    atomicAdd(&g_cnt[d4.w], 1);
}

// ---------------------------------------------------------------------------
// CSR build pass 2: exclusive prefix scan (single block, 1024 thr, int4 loads).
__global__ void scan_kernel() {
    __shared__ int partial[1024];
    const int CHUNK = 52;                 // multiple of 4; 52*1024 = CNT_PAD
    int t = threadIdx.x;
    int start = t * CHUNK;

    int sum = 0;
    #pragma unroll
    for (int i = 0; i < CHUNK / 4; i++) {
        int4 v = ((const int4*)g_cnt)[start / 4 + i];
        sum += v.x + v.y + v.z + v.w;     // padding is zero
    }
    partial[t] = sum;
    __syncthreads();

    for (int off = 1; off < 1024; off <<= 1) {
        int v = (t >= off) ? partial[t - off] : 0;
        __syncthreads();
        partial[t] += v;
        __syncthreads();
    }

    int run = (t == 0) ? 0 : partial[t - 1];
    #pragma unroll 4
    for (int i = 0; i < CHUNK; i++) {
        int idx = start + i;
        if (idx < N_NODES) {
            g_off[idx] = run;
            g_cursor[idx] = run;
            run += g_cnt[idx];
        }
    }
    if (t == 0) g_off[N_NODES] = partial[1023];
}

// ---------------------------------------------------------------------------
// CSR build pass 3: scatter edges into dst-sorted order. 8 edges/thread.
__global__ void fill_kernel(const int* __restrict__ src,
                            const int* __restrict__ dst,
                            const float* __restrict__ ew) {
    int i = blockIdx.x * blockDim.x + threadIdx.x;
    if (i >= N_EDGES / 8) return;
    int4   dA = ((const int4*)dst)[i * 2];
    int4   dB = ((const int4*)dst)[i * 2 + 1];
    int4   sA = ((const int4*)src)[i * 2];
    int4   sB = ((const int4*)src)[i * 2 + 1];
    float4 wA = ((const float4*)ew)[i * 2];
    float4 wB = ((const float4*)ew)[i * 2 + 1];
    int p0 = atomicAdd(&g_cursor[dA.x], 1);
    int p1 = atomicAdd(&g_cursor[dA.y], 1);
    int p2 = atomicAdd(&g_cursor[dA.z], 1);
    int p3 = atomicAdd(&g_cursor[dA.w], 1);
    int p4 = atomicAdd(&g_cursor[dB.x], 1);
    int p5 = atomicAdd(&g_cursor[dB.y], 1);
    int p6 = atomicAdd(&g_cursor[dB.z], 1);
    int p7 = atomicAdd(&g_cursor[dB.w], 1);
    g_csr[p0] = make_int2(sA.x, __float_as_int(wA.x));
    g_csr[p1] = make_int2(sA.y, __float_as_int(wA.y));
    g_csr[p2] = make_int2(sA.z, __float_as_int(wA.z));
    g_csr[p3] = make_int2(sA.w, __float_as_int(wA.w));
    g_csr[p4] = make_int2(sB.x, __float_as_int(wB.x));
    g_csr[p5] = make_int2(sB.y, __float_as_int(wB.y));
    g_csr[p6] = make_int2(sB.z, __float_as_int(wB.z));
    g_csr[p7] = make_int2(sB.w, __float_as_int(wB.w));
}

// ---------------------------------------------------------------------------
// Pull aggregation: one warp per node, each lane owns 2 columns (one half2
// load = 4B -> 128B fully-coalesced per edge; half the fp32 traffic).
// fp32 accumulation. Edge loop unrolled x8 for MLP.
__global__ void gather_kernel() {
    int gtid = blockIdx.x * blockDim.x + threadIdx.x;
    int node = gtid >> 5;
    if (node >= N_NODES) return;
    int lane = gtid & 31;

    int beg = g_off[node];
    int end = g_off[node + 1];

    float2 acc = make_float2(0.f, 0.f);

    int j = beg;
    for (; j + 8 <= end; j += 8) {
        int2 e0 = g_csr[j];
        int2 e1 = g_csr[j + 1];
        int2 e2 = g_csr[j + 2];
        int2 e3 = g_csr[j + 3];
        int2 e4 = g_csr[j + 4];
        int2 e5 = g_csr[j + 5];
        int2 e6 = g_csr[j + 6];
        int2 e7 = g_csr[j + 7];
        float2 v0 = __half22float2(g_h16[e0.x * 32 + lane]);
        float2 v1 = __half22float2(g_h16[e1.x * 32 + lane]);
        float2 v2 = __half22float2(g_h16[e2.x * 32 + lane]);
        float2 v3 = __half22float2(g_h16[e3.x * 32 + lane]);
        float2 v4 = __half22float2(g_h16[e4.x * 32 + lane]);
        float2 v5 = __half22float2(g_h16[e5.x * 32 + lane]);
        float2 v6 = __half22float2(g_h16[e6.x * 32 + lane]);
        float2 v7 = __half22float2(g_h16[e7.x * 32 + lane]);
        acc.x += v0.x * __int_as_float(e0.y); acc.y += v0.y * __int_as_float(e0.y);
        acc.x += v1.x * __int_as_float(e1.y); acc.y += v1.y * __int_as_float(e1.y);
        acc.x += v2.x * __int_as_float(e2.y); acc.y += v2.y * __int_as_float(e2.y);
        acc.x += v3.x * __int_as_float(e3.y); acc.y += v3.y * __int_as_float(e3.y);
        acc.x += v4.x * __int_as_float(e4.y); acc.y += v4.y * __int_as_float(e4.y);
        acc.x += v5.x * __int_as_float(e5.y); acc.y += v5.y * __int_as_float(e5.y);
        acc.x += v6.x * __int_as_float(e6.y); acc.y += v6.y * __int_as_float(e6.y);
        acc.x += v7.x * __int_as_float(e7.y); acc.y += v7.y * __int_as_float(e7.y);
    }
    for (; j < end; j++) {
        int2 e = g_csr[j];
        float w = __int_as_float(e.y);
        float2 v = __half22float2(g_h16[e.x * 32 + lane]);
        acc.x += v.x * w; acc.y += v.y * w;
    }

    ((float2*)g_agg)[node * 32 + lane] = acc;
}

// ---------------------------------------------------------------------------
// Dense transform: h_next = agg @ W + b, optional tanh.
// 64-row block, 128 threads, 8x4 register tile per thread. Writes fp32 to the
// output slab and fp16 to g_h16 (next layer's gather input).
__global__ void gemm_bias_act_kernel(const float* __restrict__ W,
                                     const float* __restrict__ b,
                                     float* __restrict__ out,
                                     int out_col_off,
                                     int do_tanh) {
    __shared__ __align__(16) float AsT[64][68];
    __shared__ __align__(16) float Wsm[64 * 64];
    __shared__ float bsh[64];

    int t = threadIdx.x;  // 128 threads
    int rowBase = blockIdx.x * 64;

    #pragma unroll
    for (int i = 0; i < 8; i++)
        ((float4*)Wsm)[t + i * 128] = ((const float4*)W)[t + i * 128];
    if (t < 64) bsh[t] = b[t];

    #pragma unroll
    for (int i = 0; i < 8; i++) {
        int idx = t + i * 128;          // 0..1023
        int row = idx >> 4;             // 0..63
        int c4  = idx & 15;
        int grow = rowBase + row;
        float4 v = (grow < N_NODES) ? ((const float4*)g_agg)[grow * 16 + c4]
                                    : make_float4(0.f, 0.f, 0.f, 0.f);
        AsT[c4 * 4 + 0][row] = v.x;
        AsT[c4 * 4 + 1][row] = v.y;
        AsT[c4 * 4 + 2][row] = v.z;
        AsT[c4 * 4 + 3][row] = v.w;
    }
    __syncthreads();

    int tx = t & 15;   // cols tx*4 .. tx*4+3
    int ty = t >> 4;   // rows ty*8 .. ty*8+7

    float acc[8][4];
    #pragma unroll
    for (int i = 0; i < 8; i++)
        #pragma unroll
        for (int j = 0; j < 4; j++)
            acc[i][j] = bsh[tx * 4 + j];

    #pragma unroll 8
    for (int k = 0; k < 64; k++) {
        float4 alo = *(const float4*)&AsT[k][ty * 8];
        float4 ahi = *(const float4*)&AsT[k][ty * 8 + 4];
        float4 w   = *(const float4*)&Wsm[k * 64 + tx * 4];
        acc[0][0] += alo.x * w.x; acc[0][1] += alo.x * w.y; acc[0][2] += alo.x * w.z; acc[0][3] += alo.x * w.w;
        acc[1][0] += alo.y * w.x; acc[1][1] += alo.y * w.y; acc[1][2] += alo.y * w.z; acc[1][3] += alo.y * w.w;
        acc[2][0] += alo.z * w.x; acc[2][1] += alo.z * w.y; acc[2][2] += alo.z * w.z; acc[2][3] += alo.z * w.w;
        acc[3][0] += alo.w * w.x; acc[3][1] += alo.w * w.y; acc[3][2] += alo.w * w.z; acc[3][3] += alo.w * w.w;
        acc[4][0] += ahi.x * w.x; acc[4][1] += ahi.x * w.y; acc[4][2] += ahi.x * w.z; acc[4][3] += ahi.x * w.w;
        acc[5][0] += ahi.y * w.x; acc[5][1] += ahi.y * w.y; acc[5][2] += ahi.y * w.z; acc[5][3] += ahi.y * w.w;
        acc[6][0] += ahi.z * w.x; acc[6][1] += ahi.z * w.y; acc[6][2] += ahi.z * w.z; acc[6][3] += ahi.z * w.w;
        acc[7][0] += ahi.w * w.x; acc[7][1] += ahi.w * w.y; acc[7][2] += ahi.w * w.z; acc[7][3] += ahi.w * w.w;
    }

    #pragma unroll
    for (int i = 0; i < 8; i++) {
        int grow = rowBase + ty * 8 + i;
        if (grow >= N_NODES) continue;
        float4 r = make_float4(acc[i][0], acc[i][1], acc[i][2], acc[i][3]);
        if (do_tanh) {
            r.x = tanhf(r.x); r.y = tanhf(r.y); r.z = tanhf(r.z); r.w = tanhf(r.w);
        }
        // fp16 copy for next layer's gather
        g_h16[grow * 32 + tx * 2 + 0] = __float22half2_rn(make_float2(r.x, r.y));
        g_h16[grow * 32 + tx * 2 + 1] = __float22half2_rn(make_float2(r.z, r.w));
        // fp32 output slab
        *(float4*)(out + (size_t)grow * 256 + out_col_off + tx * 4) = r;
    }
}

// ---------------------------------------------------------------------------
extern "C" void kernel_launch(void* const* d_in, const int* in_sizes, int n_in,
                              void* d_out, int out_size) {
    const float* h   = (const float*)d_in[0];  // [N, 64]
    const float* ew  = (const float*)d_in[1];  // [E]
    const float* Ws  = (const float*)d_in[2];  // [3, 64, 64]
    const float* bs  = (const float*)d_in[3];  // [3, 64]
    const int*   src = (const int*)d_in[4];    // [E]
    const int*   dst = (const int*)d_in[5];    // [E]
    float*       out = (float*)d_out;          // [N, 256]

    // out[:, 0:64] = h; seed g_h16; zero degree counters.
    copy_h_zero_cnt_kernel<<<(N_NODES * 16 + 255) / 256, 256>>>(h, out);

    // Build CSR (by dst) once — graph is constant across layers.
    count_kernel<<<(N_EDGES / 4 + 255) / 256, 256>>>(dst);
    scan_kernel<<<1, 1024>>>();
    fill_kernel<<<(N_EDGES / 8 + 255) / 256, 256>>>(src, dst, ew);

    for (int l = 0; l < L; l++) {
        gather_kernel<<<(N_NODES * 32 + 255) / 256, 256>>>();
        gemm_bias_act_kernel<<<(N_NODES + 63) / 64, 128>>>(
            Ws + l * 64 * 64, bs + l * 64, out, (l + 1) * 64, (l < L - 1) ? 1 : 0);
    }
}

// round 14
// speedup vs baseline: 2.1561x; 1.4501x over previous
#include <cuda_runtime.h>
#include <cuda_fp16.h>
#include <math.h>

#define N_NODES 50000
#define N_EDGES 1250000
#define D 64
#define L 3

#define CNT_PAD 53248       // >= 98*512, multiple of 4, zero-padded
#define SCAN_BLOCKS 98      // 98 * 512 = 50176 >= N_NODES

// Scratch (allocation-free).
__device__ float   g_agg[N_NODES * D];
__device__ __half2 g_h16[N_NODES * (D / 2)];   // fp16 hidden state (gather input)
__device__ int     g_cnt[CNT_PAD];             // zero at entry; scan3 re-zeroes
__device__ int     g_off[N_NODES + 1];
__device__ int     g_cursor[N_NODES];
__device__ int     g_part[SCAN_BLOCKS];
__device__ int     g_partscan[SCAN_BLOCKS];
__device__ int2    g_csr[N_EDGES];   // .x = src node, .y = weight bits

// ---------------------------------------------------------------------------
// Fused: copy h -> out[:,0:64], seed g_h16, and count in-degrees.
// g_cnt is zero on entry (static init on call 1; scan_part3 re-zeroes after).
__global__ void copy_count_kernel(const float* __restrict__ h,
                                  float* __restrict__ out,
                                  const int* __restrict__ dst) {
    int i = blockIdx.x * blockDim.x + threadIdx.x;

    if (i < N_EDGES / 4) {
        int4 d4 = ((const int4*)dst)[i];
        atomicAdd(&g_cnt[d4.x], 1);
        atomicAdd(&g_cnt[d4.y], 1);
        atomicAdd(&g_cnt[d4.z], 1);
        atomicAdd(&g_cnt[d4.w], 1);
    }

    if (i >= N_NODES * 16) return;
    int node = i >> 4;
    int c = i & 15;
    float4 v = ((const float4*)h)[i];
    ((float4*)(out + (size_t)node * 256))[c] = v;
    g_h16[node * 32 + c * 2 + 0] = __float22half2_rn(make_float2(v.x, v.y));
    g_h16[node * 32 + c * 2 + 1] = __float22half2_rn(make_float2(v.z, v.w));
}

// ---------------------------------------------------------------------------
// Scan phase 1: per-block (512-element) sums of g_cnt. 98 blocks x 256 thr.
__global__ void scan_part1_kernel() {
    __shared__ int sh[256];
    int t = threadIdx.x;
    int2 c = ((const int2*)g_cnt)[blockIdx.x * 256 + t];  // 512 ints/block
    sh[t] = c.x + c.y;
    __syncthreads();
    #pragma unroll
    for (int s = 128; s > 0; s >>= 1) {
        if (t < s) sh[t] += sh[t + s];
        __syncthreads();
    }
    if (t == 0) g_part[blockIdx.x] = sh[0];
}

// ---------------------------------------------------------------------------
// Scan phase 2: exclusive scan of the 98 block partials. 1 block, 128 thr.
__global__ void scan_part2_kernel() {
    __shared__ int sh[128];
    int t = threadIdx.x;
    sh[t] = (t < SCAN_BLOCKS) ? g_part[t] : 0;
    __syncthreads();
    #pragma unroll
    for (int off = 1; off < 128; off <<= 1) {
        int v = (t >= off) ? sh[t - off] : 0;
        __syncthreads();
        sh[t] += v;
        __syncthreads();
    }
    if (t < SCAN_BLOCKS) g_partscan[t] = (t == 0) ? 0 : sh[t - 1];
    if (t == 0) g_off[N_NODES] = sh[127];  // grand total (padding is zero)
}

// ---------------------------------------------------------------------------
// Scan phase 3: local exclusive scan within each 512-chunk + block offset.
// Writes g_off and g_cursor; re-zeroes g_cnt for the next graph replay.
__global__ void scan_part3_kernel() {
    __shared__ int sh[512];
    int t = threadIdx.x;
    int idx = blockIdx.x * 512 + t;
    int c = g_cnt[idx];                  // idx < 50176 <= CNT_PAD, pad reads 0
    sh[t] = c;
    __syncthreads();
    #pragma unroll
    for (int off = 1; off < 512; off <<= 1) {
        int v = (t >= off) ? sh[t - off] : 0;
        __syncthreads();
        sh[t] += v;
        __syncthreads();
    }
    int excl = ((t == 0) ? 0 : sh[t - 1]) + g_partscan[blockIdx.x];
    if (idx < N_NODES) {
        g_off[idx] = excl;
        g_cursor[idx] = excl;
    }
    g_cnt[idx] = 0;                      // self-clean for next replay
}

// ---------------------------------------------------------------------------
// CSR build: scatter edges into dst-sorted order. 4 edges/thread.
__global__ void fill_kernel(const int* __restrict__ src,
                            const int* __restrict__ dst,
                            const float* __restrict__ ew) {
    int i = blockIdx.x * blockDim.x + threadIdx.x;
    if (i >= N_EDGES / 4) return;
    int4   d4 = ((const int4*)dst)[i];
    int4   s4 = ((const int4*)src)[i];
    float4 w4 = ((const float4*)ew)[i];
    int p0 = atomicAdd(&g_cursor[d4.x], 1);
    int p1 = atomicAdd(&g_cursor[d4.y], 1);
    int p2 = atomicAdd(&g_cursor[d4.z], 1);
    int p3 = atomicAdd(&g_cursor[d4.w], 1);
    g_csr[p0] = make_int2(s4.x, __float_as_int(w4.x));
    g_csr[p1] = make_int2(s4.y, __float_as_int(w4.y));
    g_csr[p2] = make_int2(s4.z, __float_as_int(w4.z));
    g_csr[p3] = make_int2(s4.w, __float_as_int(w4.w));
}

// ---------------------------------------------------------------------------
// Pull aggregation: one warp per node, each lane owns 2 columns (half2 load
// = 4B -> 128B fully-coalesced per edge). fp32 accumulation, unroll x8.
__global__ void gather_kernel() {
    int gtid = blockIdx.x * blockDim.x + threadIdx.x;
    int node = gtid >> 5;
    if (node >= N_NODES) return;
    int lane = gtid & 31;

    int beg = g_off[node];
    int end = g_off[node + 1];

    float2 acc = make_float2(0.f, 0.f);

    int j = beg;
    for (; j + 8 <= end; j += 8) {
        int2 e0 = g_csr[j];
        int2 e1 = g_csr[j + 1];
        int2 e2 = g_csr[j + 2];
        int2 e3 = g_csr[j + 3];
        int2 e4 = g_csr[j + 4];
        int2 e5 = g_csr[j + 5];
        int2 e6 = g_csr[j + 6];
        int2 e7 = g_csr[j + 7];
        float2 v0 = __half22float2(g_h16[e0.x * 32 + lane]);
        float2 v1 = __half22float2(g_h16[e1.x * 32 + lane]);
        float2 v2 = __half22float2(g_h16[e2.x * 32 + lane]);
        float2 v3 = __half22float2(g_h16[e3.x * 32 + lane]);
        float2 v4 = __half22float2(g_h16[e4.x * 32 + lane]);
        float2 v5 = __half22float2(g_h16[e5.x * 32 + lane]);
        float2 v6 = __half22float2(g_h16[e6.x * 32 + lane]);
        float2 v7 = __half22float2(g_h16[e7.x * 32 + lane]);
        acc.x += v0.x * __int_as_float(e0.y); acc.y += v0.y * __int_as_float(e0.y);
        acc.x += v1.x * __int_as_float(e1.y); acc.y += v1.y * __int_as_float(e1.y);
        acc.x += v2.x * __int_as_float(e2.y); acc.y += v2.y * __int_as_float(e2.y);
        acc.x += v3.x * __int_as_float(e3.y); acc.y += v3.y * __int_as_float(e3.y);
        acc.x += v4.x * __int_as_float(e4.y); acc.y += v4.y * __int_as_float(e4.y);
        acc.x += v5.x * __int_as_float(e5.y); acc.y += v5.y * __int_as_float(e5.y);
        acc.x += v6.x * __int_as_float(e6.y); acc.y += v6.y * __int_as_float(e6.y);
        acc.x += v7.x * __int_as_float(e7.y); acc.y += v7.y * __int_as_float(e7.y);
    }
    for (; j < end; j++) {
        int2 e = g_csr[j];
        float w = __int_as_float(e.y);
        float2 v = __half22float2(g_h16[e.x * 32 + lane]);
        acc.x += v.x * w; acc.y += v.y * w;
    }

    ((float2*)g_agg)[node * 32 + lane] = acc;
}

// ---------------------------------------------------------------------------
// Dense transform: h_next = agg @ W + b, optional tanh.
// 64-row block, 128 threads, 8x4 register tile. Writes fp32 out + fp16 g_h16.
__global__ void gemm_bias_act_kernel(const float* __restrict__ W,
                                     const float* __restrict__ b,
                                     float* __restrict__ out,
                                     int out_col_off,
                                     int do_tanh) {
    __shared__ __align__(16) float AsT[64][68];
    __shared__ __align__(16) float Wsm[64 * 64];
    __shared__ float bsh[64];

    int t = threadIdx.x;  // 128 threads
    int rowBase = blockIdx.x * 64;

    #pragma unroll
    for (int i = 0; i < 8; i++)
        ((float4*)Wsm)[t + i * 128] = ((const float4*)W)[t + i * 128];
    if (t < 64) bsh[t] = b[t];

    #pragma unroll
    for (int i = 0; i < 8; i++) {
        int idx = t + i * 128;
        int row = idx >> 4;
        int c4  = idx & 15;
        int grow = rowBase + row;
        float4 v = (grow < N_NODES) ? ((const float4*)g_agg)[grow * 16 + c4]
                                    : make_float4(0.f, 0.f, 0.f, 0.f);
        AsT[c4 * 4 + 0][row] = v.x;
        AsT[c4 * 4 + 1][row] = v.y;
        AsT[c4 * 4 + 2][row] = v.z;
        AsT[c4 * 4 + 3][row] = v.w;
    }
    __syncthreads();

    int tx = t & 15;
    int ty = t >> 4;

    float acc[8][4];
    #pragma unroll
    for (int i = 0; i < 8; i++)
        #pragma unroll
        for (int j = 0; j < 4; j++)
            acc[i][j] = bsh[tx * 4 + j];

    #pragma unroll 8
    for (int k = 0; k < 64; k++) {
        float4 alo = *(const float4*)&AsT[k][ty * 8];
        float4 ahi = *(const float4*)&AsT[k][ty * 8 + 4];
        float4 w   = *(const float4*)&Wsm[k * 64 + tx * 4];
        acc[0][0] += alo.x * w.x; acc[0][1] += alo.x * w.y; acc[0][2] += alo.x * w.z; acc[0][3] += alo.x * w.w;
        acc[1][0] += alo.y * w.x; acc[1][1] += alo.y * w.y; acc[1][2] += alo.y * w.z; acc[1][3] += alo.y * w.w;
        acc[2][0] += alo.z * w.x; acc[2][1] += alo.z * w.y; acc[2][2] += alo.z * w.z; acc[2][3] += alo.z * w.w;
        acc[3][0] += alo.w * w.x; acc[3][1] += alo.w * w.y; acc[3][2] += alo.w * w.z; acc[3][3] += alo.w * w.w;
        acc[4][0] += ahi.x * w.x; acc[4][1] += ahi.x * w.y; acc[4][2] += ahi.x * w.z; acc[4][3] += ahi.x * w.w;
        acc[5][0] += ahi.y * w.x; acc[5][1] += ahi.y * w.y; acc[5][2] += ahi.y * w.z; acc[5][3] += ahi.y * w.w;
        acc[6][0] += ahi.z * w.x; acc[6][1] += ahi.z * w.y; acc[6][2] += ahi.z * w.z; acc[6][3] += ahi.z * w.w;
        acc[7][0] += ahi.w * w.x; acc[7][1] += ahi.w * w.y; acc[7][2] += ahi.w * w.z; acc[7][3] += ahi.w * w.w;
    }

    #pragma unroll
    for (int i = 0; i < 8; i++) {
        int grow = rowBase + ty * 8 + i;
        if (grow >= N_NODES) continue;
        float4 r = make_float4(acc[i][0], acc[i][1], acc[i][2], acc[i][3]);
        if (do_tanh) {
            r.x = tanhf(r.x); r.y = tanhf(r.y); r.z = tanhf(r.z); r.w = tanhf(r.w);
        }
        g_h16[grow * 32 + tx * 2 + 0] = __float22half2_rn(make_float2(r.x, r.y));
        g_h16[grow * 32 + tx * 2 + 1] = __float22half2_rn(make_float2(r.z, r.w));
        *(float4*)(out + (size_t)grow * 256 + out_col_off + tx * 4) = r;
    }
}

// ---------------------------------------------------------------------------
extern "C" void kernel_launch(void* const* d_in, const int* in_sizes, int n_in,
                              void* d_out, int out_size) {
    const float* h   = (const float*)d_in[0];  // [N, 64]
    const float* ew  = (const float*)d_in[1];  // [E]
    const float* Ws  = (const float*)d_in[2];  // [3, 64, 64]
    const float* bs  = (const float*)d_in[3];  // [3, 64]
    const int*   src = (const int*)d_in[4];    // [E]
    const int*   dst = (const int*)d_in[5];    // [E]
    float*       out = (float*)d_out;          // [N, 256]

    // Fused copy + degree count (g_cnt zero on entry; scan3 re-zeroes).
    copy_count_kernel<<<(N_NODES * 16 + 255) / 256, 256>>>(h, out, dst);

    // Parallel 3-phase exclusive scan -> g_off / g_cursor.
    scan_part1_kernel<<<SCAN_BLOCKS, 256>>>();
    scan_part2_kernel<<<1, 128>>>();
    scan_part3_kernel<<<SCAN_BLOCKS, 512>>>();

    // CSR fill (by dst).
    fill_kernel<<<(N_EDGES / 4 + 255) / 256, 256>>>(src, dst, ew);

    for (int l = 0; l < L; l++) {
        gather_kernel<<<(N_NODES * 32 + 255) / 256, 256>>>();
        gemm_bias_act_kernel<<<(N_NODES + 63) / 64, 128>>>(
            Ws + l * 64 * 64, bs + l * 64, out, (l + 1) * 64, (l < L - 1) ? 1 : 0);
    }
}